// round 1
// baseline (speedup 1.0000x reference)
#include <cuda_runtime.h>
#include <cuda_bf16.h>

// CTC-style forward scan.
//   x:        (nt, nb, 5)  float32
//   seqs:     (nb, ns)     int32 in [0,4)
//   seqlens:  (nb,)        int32 in [0, ns]
//   out:      (nb,)        float32 = -fwd[nt][seqlen[b]] / nt
//
// Recurrence (per batch b):
//   fwd_0[0] = 0, fwd_0[j>0] = -1e30
//   fwd_{t+1}[0] = x[t,b,4] + fwd_t[0]
//   fwd_{t+1}[j] = logaddexp(x[t,b,seqs[b,j-1]] + fwd_t[j-1],
//                            x[t,b,4]           + fwd_t[j])      (j >= 1)
//
// Mapping: one CTA per batch. 128 threads x 4 contiguous positions each
// (covers ns+1 = 501 <= 512). DP state lives in registers; the single
// cross-thread dependency (left neighbor's last position) goes through a
// double-buffered shared halo with ONE __syncthreads per timestep.
// x[t,b,0..4] staged in shared, 32 timesteps per chunk, double buffered,
// prefetched one chunk ahead.
//
// Work skipping:
//  - positions j > seqlen[b] can never reach the output slot (j only
//    increases over time): those threads skip all math forever.
//  - wavefront: fwd[j] stays -1e30 until t+1 >= j, so a thread skips math
//    while t < jmin-1. Skipped threads still hit the barrier and help with
//    x-chunk loads, and the halo buffers are pre-initialized to -1e30 so
//    their (unwritten) halo slots are already correct.

#define TPB   128
#define P     4
#define XCH   32
#define NEGF  (-1e30f)

__device__ __forceinline__ float lae(float a, float b) {
    // logaddexp(a,b) = max + log(1 + exp(min - max)); min-max <= 0 so
    // __expf is in (0,1] and __logf(1+e) is well conditioned. Matches the
    // reference's -1e30 sentinel arithmetic in fp32.
    float m = fmaxf(a, b);
    float d = fminf(a, b) - m;
    return m + __logf(1.0f + __expf(d));
}

__global__ __launch_bounds__(TPB, 2)
void ctc_fwd_kernel(const float* __restrict__ x,
                    const int*   __restrict__ seqs,
                    const int*   __restrict__ seqlens,
                    float*       __restrict__ out,
                    int nt, int nb, int ns)
{
    __shared__ float halo[2][TPB + 1];   // halo[buf][i] = fwd[i*P - 1]
    __shared__ float shx[2][XCH][8];     // [buf][t_in_chunk][feature(5, pad 8)]
    __shared__ float shf[TPB * P];       // final fwd gather

    const int b    = blockIdx.x;
    const int tid  = threadIdx.x;
    const int jmin = tid * P;
    const int sl   = seqlens[b];

    // init halo buffers to -inf (both parities)
    for (int i = tid; i < TPB + 1; i += TPB) {
        halo[0][i] = NEGF;
        halo[1][i] = NEGF;
    }

    // per-position move-feature index (time-invariant); j==0 has no move
    // (left halo is -inf so its contribution is dead regardless).
    int s0, s1, s2, s3;
    {
        const int* sb = seqs + (long long)b * ns;
        int j;
        j = jmin + 0; s0 = (j >= 1 && j <= ns) ? sb[j - 1] : 0;
        j = jmin + 1; s1 = (j >= 1 && j <= ns) ? sb[j - 1] : 0;
        j = jmin + 2; s2 = (j >= 1 && j <= ns) ? sb[j - 1] : 0;
        j = jmin + 3; s3 = (j >= 1 && j <= ns) ? sb[j - 1] : 0;
    }

    float f0 = (jmin == 0) ? 0.0f : NEGF;
    float f1 = NEGF, f2 = NEGF, f3 = NEGF;

    const bool dead   = (jmin > sl);          // can never influence out[b]
    const long long xstride = (long long)nb * 5;
    const float* xb = x + (long long)b * 5;

    // chunk c covers timesteps [c*XCH, c*XCH+XCH)
    auto load_chunk = [&](int c) {
        const int tbase = c * XCH;
        if (tbase >= nt) return;
        const int buf = c & 1;
        #pragma unroll
        for (int i = tid; i < XCH * 5; i += TPB) {
            int tt = tbase + i / 5;
            int ff = i - (i / 5) * 5;
            if (tt < nt)
                shx[buf][i / 5][ff] = xb[(long long)tt * xstride + ff];
        }
    };

    load_chunk(0);   // visible after the t=0 barrier below

    for (int t = 0; t < nt; ++t) {
        __syncthreads();   // (a) halo writes of step t-1 / init visible
                           // (b) WAR: step t-1 reads done before step t writes
        const int ph = t & (XCH - 1);
        const int cb = (t >> 5) & 1;
        if (ph == 0) load_chunk((t >> 5) + 1);   // prefetch next chunk

        if (!dead && t >= jmin - 1) {
            const float* xr  = shx[cb][ph];
            const float  x4  = xr[4];
            const float  left = halo[t & 1][tid];

            float n0 = lae(xr[s0] + left, x4 + f0);
            float n1 = lae(xr[s1] + f0,   x4 + f1);
            float n2 = lae(xr[s2] + f1,   x4 + f2);
            float n3 = lae(xr[s3] + f2,   x4 + f3);
            f0 = n0; f1 = n1; f2 = n2; f3 = n3;

            halo[(t + 1) & 1][tid + 1] = f3;
        }
    }

    __syncthreads();
    shf[jmin + 0] = f0;
    shf[jmin + 1] = f1;
    shf[jmin + 2] = f2;
    shf[jmin + 3] = f3;
    __syncthreads();

    if (tid == 0)
        out[b] = -shf[sl] / (float)nt;
}

extern "C" void kernel_launch(void* const* d_in, const int* in_sizes, int n_in,
                              void* d_out, int out_size) {
    const float* x       = (const float*)d_in[0];
    const int*   seqs    = (const int*)  d_in[1];
    const int*   seqlens = (const int*)  d_in[2];
    float*       out     = (float*)d_out;

    const int nb = in_sizes[2];
    const int ns = in_sizes[1] / nb;
    const int nt = in_sizes[0] / (nb * 5);

    ctc_fwd_kernel<<<nb, TPB>>>(x, seqs, seqlens, out, nt, nb, ns);
}

// round 3
// speedup vs baseline: 2.7296x; 2.7296x over previous
#include <cuda_runtime.h>
#include <cuda_bf16.h>

// CTC forward scan, linear domain with x4-factored recurrence:
//   G_j(t+1) = W_t[s_j] * G_{j-1}(t) + G_j(t),   W_t[s] = exp(x[t,s] - x[t,4])
//   fwd[j](t) = log(G_j) + e_j*ln2 + sum_t x4(t)
//
// Trapezoidal tiling: thread owns 8 positions (G[4..11]) and keeps a 4-wide
// redundant left overlap (G[0..3], refreshed from the left neighbor's halo
// each region), allowing 4 timesteps per CTA barrier. Validity shrinks one
// position per step from the left; after 4 steps the owned 8 are exact.
//
// Scaling: per-thread power-of-2 exponent e, renormalized each region.
// Cross-thread mixing uses the COMMON scale c = max(e, eL): both rescale
// factors are <= 1 => post-rescale values <= 2, region growth <= prod(1+W)
// => no overflow; the smaller side underflowing to 0 is correct (negligible).
//
// 64 threads per batch (8*64=512 >= ns+1=501), 2 batches per CTA -> 128 CTAs
// ~ 1 per SM. Warp 1 of each batch doubles as the W-chunk loader (32 steps,
// double buffered) and accumulates sum(x4) in double. Steps beyond nt are
// padded with W=0 (G frozen => exact).

#define PB   8
#define KB   4
#define LT   64
#define TPB  128
#define XCH  32
#define NREG (XCH / KB)

__device__ __forceinline__ float exp2i_le(int d) {
    // 2^d for d <= 0 (flush to 0 below 2^-127), clamped safe for any d
    int b = d + 127;
    b = b < 0 ? 0 : (b > 254 ? 254 : b);
    return __int_as_float(b << 23);
}

__global__ __launch_bounds__(TPB, 1)
void ctc_fwd(const float* __restrict__ x,
             const int*   __restrict__ seqs,
             const int*   __restrict__ seqlens,
             float*       __restrict__ out,
             int nt, int nb, int ns)
{
    __shared__ float4 shW  [2][2][XCH];      // [batch][buf][tau] = W[0..3]
    __shared__ float4 haloF[2][2][LT + 1];   // [batch][parity][slot]
    __shared__ int    haloE[2][2][LT + 1];
    __shared__ float  gall [2][LT * PB];
    __shared__ int    eall [2][LT];
    __shared__ double dsum [2][32];

    const int tid   = threadIdx.x;
    const int batch = tid >> 6;
    const int l     = tid & 63;
    const int bb    = blockIdx.x * 2 + batch;
    const bool bvalid = (bb < nb);
    const int sl    = bvalid ? seqlens[bb] : -1;
    const int jmin  = l * PB;

    // init halo buffers (both parities) to zero
    {
        float4* hf = &haloF[0][0][0];
        int*    he = &haloE[0][0][0];
        for (int i = tid; i < 2 * 2 * (LT + 1); i += TPB) {
            hf[i] = make_float4(0.f, 0.f, 0.f, 0.f);
            he[i] = 0;
        }
    }

    // move-feature indices for the 11 updated positions (G[1..11] =
    // positions jmin-3 .. jmin+7; position j uses seqs[j-1])
    int s[11];
    #pragma unroll
    for (int i = 0; i < 11; ++i) {
        int q = jmin + i - 4;                 // = j-1 for target j
        s[i] = (bvalid && q >= 0 && q < ns) ? seqs[(long long)bb * ns + q] : 0;
    }

    float G[12];
    #pragma unroll
    for (int i = 0; i < 12; ++i) G[i] = 0.0f;
    if (l == 0 && bvalid) G[4] = 1.0f;        // position 0: fwd=0 -> G=1
    int  e = 0;
    bool hasmass = (l == 0 && bvalid);

    double x4s = 0.0;
    auto load_chunk = [&](int c) {
        if (l >= 32 && bvalid) {
            const int tau = l - 32;
            const int tt  = c * XCH + tau;
            float4 w = make_float4(0.f, 0.f, 0.f, 0.f);
            if (tt < nt) {
                const float* xp = x + ((long long)tt * nb + bb) * 5;
                float a0 = xp[0], a1 = xp[1], a2 = xp[2], a3 = xp[3], a4 = xp[4];
                w.x = __expf(a0 - a4);
                w.y = __expf(a1 - a4);
                w.z = __expf(a2 - a4);
                w.w = __expf(a3 - a4);
                x4s += (double)a4;
            }
            shW[batch][c & 1][tau] = w;
        }
    };

    load_chunk(0);

    const int NC = (nt + XCH - 1) / XCH;
    for (int c = 0; c < NC; ++c) {
        const float* wbase = &shW[batch][c & 1][0].x;
        const float* wp[11];
        #pragma unroll
        for (int i = 0; i < 11; ++i) wp[i] = wbase + s[i];

        #pragma unroll
        for (int r = 0; r < NREG; ++r) {
            __syncthreads();                  // halo r-parity visible; WAR safe
            if (r == 0) load_chunk(c + 1);    // prefetch next chunk

            const int par = r & 1;
            float4 LH = haloF[batch][par][l];
            int    eL = haloE[batch][par][l];
            float lmax = fmaxf(fmaxf(LH.x, LH.y), fmaxf(LH.z, LH.w));
            bool act = (jmin <= sl) && (hasmass || lmax > 0.0f);

            if (act) {
                // common scale: both factors <= 1 -> overflow impossible
                int eo  = hasmass ? e : eL;           // adopt left scale if empty
                int el2 = (lmax > 0.0f) ? eL : eo;
                int cc  = eo > el2 ? eo : el2;
                float rs = exp2i_le(eo - cc);
                float rl = exp2i_le(eL - cc);

                G[0] = LH.x * rl; G[1] = LH.y * rl;
                G[2] = LH.z * rl; G[3] = LH.w * rl;
                #pragma unroll
                for (int i = 4; i < 12; ++i) G[i] *= rs;
                e = cc;

                #pragma unroll
                for (int k = 0; k < KB; ++k) {
                    const int tau = r * KB + k;
                    #pragma unroll
                    for (int i = 10; i >= 0; --i)      // in-place, descending
                        G[i + 1] = fmaf(wp[i][tau * 4], G[i], G[i + 1]);
                }

                float mx = G[4];
                #pragma unroll
                for (int i = 5; i < 12; ++i) mx = fmaxf(mx, G[i]);
                hasmass = (mx > 0.0f);
                if (hasmass) {
                    int ex = (__float_as_int(mx) >> 23) - 127;
                    float sc = __int_as_float((127 - ex) << 23);  // 2^-ex
                    #pragma unroll
                    for (int i = 4; i < 12; ++i) G[i] *= sc;
                    e += ex;
                    haloF[batch][par ^ 1][l + 1] =
                        make_float4(G[8], G[9], G[10], G[11]);
                    haloE[batch][par ^ 1][l + 1] = e;
                }
            }
        }
    }

    __syncthreads();
    #pragma unroll
    for (int i = 0; i < PB; ++i) gall[batch][jmin + i] = G[4 + i];
    eall[batch][l] = e;
    if (l >= 32) dsum[batch][l - 32] = x4s;
    __syncthreads();

    if (l == 0 && bvalid) {
        double xs = 0.0;
        #pragma unroll
        for (int i = 0; i < 32; ++i) xs += dsum[batch][i];
        float Gv = gall[batch][sl];
        int   ev = eall[batch][sl >> 3];
        double lv = (double)logf(Gv) + (double)ev * 0.6931471805599453 + xs;
        out[bb] = (float)(-lv / (double)nt);
    }
}

extern "C" void kernel_launch(void* const* d_in, const int* in_sizes, int n_in,
                              void* d_out, int out_size) {
    const float* x       = (const float*)d_in[0];
    const int*   seqs    = (const int*)  d_in[1];
    const int*   seqlens = (const int*)  d_in[2];
    float*       out     = (float*)d_out;

    const int nb = in_sizes[2];
    const int ns = in_sizes[1] / nb;
    const int nt = in_sizes[0] / (nb * 5);

    ctc_fwd<<<(nb + 1) / 2, TPB>>>(x, seqs, seqlens, out, nt, nb, ns);
}

// round 5
// speedup vs baseline: 3.0200x; 1.1064x over previous
#include <cuda_runtime.h>
#include <cuda_bf16.h>

// CTC forward scan, linear domain, x4-factored:
//   G_j(t+1) = W_t[s_j]*G_{j-1}(t) + G_j(t),  W_t[s] = exp(x[t,s]-x[t,4])
//   fwd[j] = log(G_j) + e*ln2 + sum_t x4
//
// R4 structure:
//  - one 128-thread CTA = TWO independent 64-thread batch groups, each with
//    its own named barrier (bar.sync 1+grp, 64) -> batches never couple.
//  - trapezoid K=8: thread owns 8 positions (G[8..15]) + 8-wide left overlap
//    (G[0..7] refreshed from left neighbor's halo), 8 steps per barrier.
//  - software-pipelined x loads: LDG for chunk c+2 issued one chunk ahead of
//    its exp+STS conversion, so no barrier ever waits on global memory.
//  - scaling: per-thread pow2 exponent, common-scale mixing (max of own/left)
//    so every rescale factor is <= 1 -> overflow impossible; halo is sent
//    post-renorm (values in [0,2)) so 8-step growth stays far below 2^127.

#define LT    64
#define PB    8
#define KB    8
#define XCH   32
#define NREG  (XCH / KB)
#define TPB   128

#define GBAR() asm volatile("bar.sync %0, %1;" :: "r"(grp + 1), "n"(64) : "memory")

__device__ __forceinline__ float exp2i_le(int d) {
    // 2^d clamped into [2^-127, 2^127]; flush below to 0
    int b = d + 127;
    b = b < 0 ? 0 : (b > 254 ? 254 : b);
    return __int_as_float(b << 23);
}

__global__ __launch_bounds__(TPB, 1)
void ctc_fwd(const float* __restrict__ x,
             const int*   __restrict__ seqs,
             const int*   __restrict__ seqlens,
             float*       __restrict__ out,
             int nt, int nb, int ns)
{
    __shared__ float4 hA[2][2][LT + 1];    // [grp][parity][slot] G[8..11]
    __shared__ float4 hB[2][2][LT + 1];    //                    G[12..15]
    __shared__ int    hE[2][2][LT + 1];
    __shared__ float  shW[2][2][XCH * 4];  // [grp][buf][tau*4 + s]
    __shared__ float  gall[2][LT * PB];
    __shared__ int    eall[2][LT];
    __shared__ double ds[2];

    const int  tid  = threadIdx.x;
    const int  grp  = tid >> 6;
    const int  l    = tid & 63;
    const int  bb   = blockIdx.x * 2 + grp;
    const bool bv   = (bb < nb);
    const int  sl   = bv ? seqlens[bb] : -1;
    const int  jmin = l * PB;

    // init halo slots (both parities) to zero
    for (int i = tid; i < 2 * 2 * (LT + 1); i += TPB) {
        ((float4*)hA)[i] = make_float4(0.f, 0.f, 0.f, 0.f);
        ((float4*)hB)[i] = make_float4(0.f, 0.f, 0.f, 0.f);
        ((int*)hE)[i] = 0;
    }

    // move-feature indices: update target G[i+1] = position jmin+i-7,
    // uses seqs[position-1] = seqs[jmin+i-8]
    int s[15];
    #pragma unroll
    for (int k = 0; k < 15; ++k) {
        int q = jmin + k - 8;
        s[k] = (bv && q >= 0 && q < ns) ? seqs[(long long)bb * ns + q] : 0;
    }

    float G[16];
    #pragma unroll
    for (int i = 0; i < 16; ++i) G[i] = 0.0f;
    if (l == 0 && bv) G[8] = 1.0f;          // position 0: fwd=0 -> G=1
    int  e = 0;
    bool hasmass = (l == 0 && bv);

    // x loader: lanes 32..63 of each group, one timestep per lane
    const bool isload = (l >= 32) && bv;
    const int  tau    = l - 32;
    float a0 = 0.f, a1 = 0.f, a2 = 0.f, a3 = 0.f, a4 = 0.f;
    double x4s = 0.0;

    auto prefetch = [&](int c) {            // LDG only (into registers)
        if (isload) {
            int tt = c * XCH + tau;
            if (tt < nt) {
                const float* xp = x + ((long long)tt * nb + bb) * 5;
                a0 = xp[0]; a1 = xp[1]; a2 = xp[2]; a3 = xp[3]; a4 = xp[4];
            } else {
                a0 = a1 = a2 = a3 = -1e9f;  // exp -> 0: steps past nt freeze G
                a4 = 0.f;
            }
        }
    };
    auto convert = [&](int c) {             // expf + STS (regs staged earlier)
        if (isload) {
            float* wr = &shW[grp][c & 1][tau * 4];
            wr[0] = __expf(a0 - a4);
            wr[1] = __expf(a1 - a4);
            wr[2] = __expf(a2 - a4);
            wr[3] = __expf(a3 - a4);
            if (c * XCH + tau < nt) x4s += (double)a4;
        }
    };

    prefetch(0);
    convert(0);          // one-time startup stall, negligible
    prefetch(1);
    GBAR();              // halo init + W buf0 visible to the group

    const int NC = (nt + XCH - 1) / XCH;
    for (int c = 0; c < NC; ++c) {
        const float* wb = &shW[grp][c & 1][0];
        for (int r = 0; r < NREG; ++r) {
            GBAR();                          // prev region halos visible; WAR
            if (r == NREG - 1) {             // pipeline: convert c+1, fetch c+2
                convert(c + 1);
                prefetch(c + 2);
            }

            const int par = r & 1;           // NREG even -> global alternation
            float4 A  = hA[grp][par][l];
            float4 B  = hB[grp][par][l];
            int    eL = hE[grp][par][l];
            float lmax = fmaxf(fmaxf(fmaxf(A.x, A.y), fmaxf(A.z, A.w)),
                               fmaxf(fmaxf(B.x, B.y), fmaxf(B.z, B.w)));
            bool act = (jmin <= sl) && (hasmass || lmax > 0.0f);

            if (act) {
                // common scale: both factors <= 1 -> no overflow
                int eo  = hasmass ? e : eL;
                int el2 = (lmax > 0.0f) ? eL : eo;
                int cc  = eo > el2 ? eo : el2;
                float rl = exp2i_le(eL - cc);
                float rs = exp2i_le(eo - cc);
                G[0] = A.x * rl; G[1] = A.y * rl; G[2] = A.z * rl; G[3] = A.w * rl;
                G[4] = B.x * rl; G[5] = B.y * rl; G[6] = B.z * rl; G[7] = B.w * rl;
                #pragma unroll
                for (int i = 8; i < 16; ++i) G[i] *= rs;
                e = cc;

                const float* wreg = wb + (r * KB) * 4;
                #pragma unroll
                for (int k = 0; k < KB; ++k) {
                    const float* wk = wreg + k * 4;
                    #pragma unroll
                    for (int i = 14; i >= 0; --i)      // in-place, descending
                        G[i + 1] = fmaf(wk[s[i]], G[i], G[i + 1]);
                }

                float mx = G[8];
                #pragma unroll
                for (int i = 9; i < 16; ++i) mx = fmaxf(mx, G[i]);
                hasmass = (mx > 0.0f);
                if (hasmass) {
                    int ex = (__float_as_int(mx) >> 23) - 127;
                    float sc = __int_as_float((127 - ex) << 23);  // 2^-ex
                    #pragma unroll
                    for (int i = 8; i < 16; ++i) G[i] *= sc;
                    e += ex;
                    hA[grp][par ^ 1][l + 1] = make_float4(G[8],  G[9],  G[10], G[11]);
                    hB[grp][par ^ 1][l + 1] = make_float4(G[12], G[13], G[14], G[15]);
                    hE[grp][par ^ 1][l + 1] = e;
                }
            }
        }
    }

    GBAR();
    #pragma unroll
    for (int i = 0; i < PB; ++i) gall[grp][jmin + i] = G[8 + i];
    eall[grp][l] = e;
    if (isload) {                           // reduce sum(x4) within loader warp
        double v = x4s;
        #pragma unroll
        for (int o = 16; o; o >>= 1)
            v += __shfl_down_sync(0xffffffffu, v, o);
        if (tau == 0) ds[grp] = v;
    }
    GBAR();

    if (l == 0 && bv) {
        float  Gv = gall[grp][sl];
        int    ev = eall[grp][sl >> 3];
        double lv = (double)logf(Gv) + (double)ev * 0.6931471805599453 + ds[grp];
        out[bb] = (float)(-lv / (double)nt);
    }
}

extern "C" void kernel_launch(void* const* d_in, const int* in_sizes, int n_in,
                              void* d_out, int out_size) {
    const float* x       = (const float*)d_in[0];
    const int*   seqs    = (const int*)  d_in[1];
    const int*   seqlens = (const int*)  d_in[2];
    float*       out     = (float*)d_out;

    const int nb = in_sizes[2];
    const int ns = in_sizes[1] / nb;
    const int nt = in_sizes[0] / (nb * 5);

    ctc_fwd<<<(nb + 1) / 2, TPB>>>(x, seqs, seqlens, out, nt, nb, ns);
}

// round 7
// speedup vs baseline: 3.2007x; 1.0598x over previous
#include <cuda_runtime.h>

// CTC forward scan, linear domain, x4-factored (R5 kernel, resubmitted —
// previous round was a container infra failure, never executed):
//   G_j(t+1) = W_t[s_j]*G_{j-1}(t) + G_j(t),  W_t[s] = exp(x[t,s]-x[t,4])
//   fwd[j] = log(G_j) + e*ln2 + sum_t x4
//
// Pair-table W staging. Loader writes, per timestep tau, all 16
// (W[a],W[b]) float2 combos; the 15-FFMA ladder then needs only 8 LDS.64
// per step (each pair feeds two FFMAs), double-buffered across steps so
// LDS latency hides behind FFMAs. Table rows padded to 33 float2 (264 B)
// => loader STS.64 (lane==tau, fixed row) and compute LDS.64 (random row,
// fixed tau) are both conflict-free.
//
// One batch per 64-thread CTA (grid=nb=256 -> all 148 SMs busy).
// Trapezoid K=8: thread owns positions jmin..jmin+7 in G[8..15] plus an
// 8-wide redundant left overlap G[0..7] refreshed from the left neighbor's
// halo each region; 8 timesteps per __syncthreads.
// Scaling: per-thread pow2 exponent, common-scale mixing (factors <= 1 =>
// no overflow); halo sent post-renorm (values in [0,2)).

#define LT    64
#define PB    8
#define KB    8
#define XCH   32
#define NREG  (XCH / KB)
#define TPB   64
#define PSTR  33      // float2 per table row (264 B): conflict-free both ways

__device__ __forceinline__ float exp2i_le(int d) {
    int b = d + 127;
    b = b < 0 ? 0 : (b > 254 ? 254 : b);
    return __int_as_float(b << 23);
}

__global__ __launch_bounds__(TPB, 2)
void ctc_fwd(const float* __restrict__ x,
             const int*   __restrict__ seqs,
             const int*   __restrict__ seqlens,
             float*       __restrict__ out,
             int nt, int nb, int ns)
{
    __shared__ float2 shP[2][16 * PSTR];   // [buf][p*PSTR + tau]
    __shared__ float4 hA[2][LT + 1];       // halo G[8..11]
    __shared__ float4 hB[2][LT + 1];       // halo G[12..15]
    __shared__ int    hE[2][LT + 1];
    __shared__ float  gall[LT * PB];
    __shared__ int    eall[LT];
    __shared__ double ds;

    const int  tid  = threadIdx.x;
    const int  l    = tid;
    const int  bb   = blockIdx.x;
    const int  sl   = seqlens[bb];
    const int  jmin = l * PB;

    for (int i = tid; i < 2 * (LT + 1); i += TPB) {
        ((float4*)hA)[i] = make_float4(0.f, 0.f, 0.f, 0.f);
        ((float4*)hB)[i] = make_float4(0.f, 0.f, 0.f, 0.f);
        ((int*)hE)[i] = 0;
    }

    // move indices: ladder target G[i+1] uses seqs[jmin+i-8], i=0..14
    int s[16];
    #pragma unroll
    for (int k = 0; k < 15; ++k) {
        int q = jmin + k - 8;
        s[k] = (q >= 0 && q < ns) ? seqs[(long long)bb * ns + q] : 0;
    }
    s[15] = s[14];                          // pad: pair 7 = (s14, s14)
    int pq[8];                              // row offsets (in float2 units)
    #pragma unroll
    for (int q = 0; q < 8; ++q)
        pq[q] = (s[2 * q] * 4 + s[2 * q + 1]) * PSTR;

    float G[16];
    #pragma unroll
    for (int i = 0; i < 16; ++i) G[i] = 0.0f;
    if (l == 0) G[8] = 1.0f;                // position 0: fwd=0 -> G=1
    int  e = 0;
    bool hasmass = (l == 0);

    // loader: lanes 32..63 (warp 1), one timestep per lane
    const bool isload = (l >= 32);
    const int  tau    = l - 32;
    float a0 = 0.f, a1 = 0.f, a2 = 0.f, a3 = 0.f, a4 = 0.f;
    double x4s = 0.0;

    auto prefetch = [&](int c) {            // LDG only
        if (isload) {
            int tt = c * XCH + tau;
            if (tt < nt) {
                const float* xp = x + ((long long)tt * nb + bb) * 5;
                a0 = xp[0]; a1 = xp[1]; a2 = xp[2]; a3 = xp[3]; a4 = xp[4];
            } else {
                a0 = a1 = a2 = a3 = -1e9f;  // exp->0: steps past nt freeze G
                a4 = 0.f;
            }
        }
    };
    auto convert = [&](int c) {             // expf + 16 STS.64
        if (isload) {
            float w[4];
            w[0] = __expf(a0 - a4);
            w[1] = __expf(a1 - a4);
            w[2] = __expf(a2 - a4);
            w[3] = __expf(a3 - a4);
            float2* row = &shP[c & 1][tau];
            #pragma unroll
            for (int a = 0; a < 4; ++a)
                #pragma unroll
                for (int bq = 0; bq < 4; ++bq)
                    row[(a * 4 + bq) * PSTR] = make_float2(w[a], w[bq]);
            if (c * XCH + tau < nt) x4s += (double)a4;
        }
    };

    prefetch(0);
    convert(0);
    prefetch(1);
    __syncthreads();

    const int NC = (nt + XCH - 1) / XCH;
    for (int c = 0; c < NC; ++c) {
        const float2* cbase = &shP[c & 1][0];
        for (int r = 0; r < NREG; ++r) {
            __syncthreads();                 // prev region halos visible; WAR
            if (r == NREG - 1) {             // pipeline: convert c+1, fetch c+2
                convert(c + 1);
                prefetch(c + 2);
            }

            const int par = r & 1;           // NREG even -> global alternation
            float4 A  = hA[par][l];
            float4 B  = hB[par][l];
            int    eL = hE[par][l];
            float lmax = fmaxf(fmaxf(fmaxf(A.x, A.y), fmaxf(A.z, A.w)),
                               fmaxf(fmaxf(B.x, B.y), fmaxf(B.z, B.w)));
            bool act = (jmin <= sl) && (hasmass || lmax > 0.0f);

            if (act) {
                // common scale: both factors <= 1 -> no overflow
                int eo  = hasmass ? e : eL;
                int el2 = (lmax > 0.0f) ? eL : eo;
                int cc  = eo > el2 ? eo : el2;
                float rl = exp2i_le(eL - cc);
                float rs = exp2i_le(eo - cc);
                G[0] = A.x * rl; G[1] = A.y * rl; G[2] = A.z * rl; G[3] = A.w * rl;
                G[4] = B.x * rl; G[5] = B.y * rl; G[6] = B.z * rl; G[7] = B.w * rl;
                #pragma unroll
                for (int i = 8; i < 16; ++i) G[i] *= rs;
                e = cc;

                // per-q row pointers for this region's 8 taus
                const float2* rp0 = cbase + pq[0] + r * KB;
                const float2* rp1 = cbase + pq[1] + r * KB;
                const float2* rp2 = cbase + pq[2] + r * KB;
                const float2* rp3 = cbase + pq[3] + r * KB;
                const float2* rp4 = cbase + pq[4] + r * KB;
                const float2* rp5 = cbase + pq[5] + r * KB;
                const float2* rp6 = cbase + pq[6] + r * KB;
                const float2* rp7 = cbase + pq[7] + r * KB;

                float2 W0[8], W1[8];
                W0[0] = rp0[0]; W0[1] = rp1[0]; W0[2] = rp2[0]; W0[3] = rp3[0];
                W0[4] = rp4[0]; W0[5] = rp5[0]; W0[6] = rp6[0]; W0[7] = rp7[0];

                #pragma unroll
                for (int k = 0; k < KB; ++k) {
                    float2* cur = (k & 1) ? W1 : W0;
                    float2* nxt = (k & 1) ? W0 : W1;
                    if (k < KB - 1) {        // prefetch next step's pairs
                        nxt[0] = rp0[k + 1]; nxt[1] = rp1[k + 1];
                        nxt[2] = rp2[k + 1]; nxt[3] = rp3[k + 1];
                        nxt[4] = rp4[k + 1]; nxt[5] = rp5[k + 1];
                        nxt[6] = rp6[k + 1]; nxt[7] = rp7[k + 1];
                    }
                    // descending i: i=14 then (13,12),(11,10),...,(1,0)
                    G[15] = fmaf(cur[7].x, G[14], G[15]);
                    #pragma unroll
                    for (int q = 6; q >= 0; --q) {
                        G[2 * q + 2] = fmaf(cur[q].y, G[2 * q + 1], G[2 * q + 2]);
                        G[2 * q + 1] = fmaf(cur[q].x, G[2 * q],     G[2 * q + 1]);
                    }
                }

                float mx = G[8];
                #pragma unroll
                for (int i = 9; i < 16; ++i) mx = fmaxf(mx, G[i]);
                hasmass = (mx > 0.0f);
                if (hasmass) {
                    int ex = (__float_as_int(mx) >> 23) - 127;
                    float sc = __int_as_float((127 - ex) << 23);  // 2^-ex
                    #pragma unroll
                    for (int i = 8; i < 16; ++i) G[i] *= sc;
                    e += ex;
                    hA[par ^ 1][l + 1] = make_float4(G[8],  G[9],  G[10], G[11]);
                    hB[par ^ 1][l + 1] = make_float4(G[12], G[13], G[14], G[15]);
                    hE[par ^ 1][l + 1] = e;
                }
            }
        }
    }

    __syncthreads();
    #pragma unroll
    for (int i = 0; i < PB; ++i) gall[jmin + i] = G[8 + i];
    eall[l] = e;
    if (isload) {                           // reduce sum(x4) in loader warp
        double v = x4s;
        #pragma unroll
        for (int o = 16; o; o >>= 1)
            v += __shfl_down_sync(0xffffffffu, v, o);
        if (tau == 0) ds = v;
    }
    __syncthreads();

    if (l == 0) {
        float  Gv = gall[sl];
        int    ev = eall[sl >> 3];
        double lv = (double)logf(Gv) + (double)ev * 0.6931471805599453 + ds;
        out[bb] = (float)(-lv / (double)nt);
    }
}

extern "C" void kernel_launch(void* const* d_in, const int* in_sizes, int n_in,
                              void* d_out, int out_size) {
    const float* x       = (const float*)d_in[0];
    const int*   seqs    = (const int*)  d_in[1];
    const int*   seqlens = (const int*)  d_in[2];
    float*       out     = (float*)d_out;

    const int nb = in_sizes[2];
    const int ns = in_sizes[1] / nb;
    const int nt = in_sizes[0] / (nb * 5);

    ctc_fwd<<<nb, TPB>>>(x, seqs, seqlens, out, nt, nb, ns);
}

// round 9
// speedup vs baseline: 3.3271x; 1.0395x over previous
#include <cuda_runtime.h>

// CTC forward scan, linear domain, x4-factored:
//   G_j(t+1) = W_t[s_j]*G_{j-1}(t) + G_j(t),  W_t[s] = exp(x[t,s]-x[t,4])
//   fwd[j] = log2-scaled G + e*ln2 + sum_t x4
//
// R7: ONE WARP PER BATCH — zero barriers.
//  - 32 lanes x PB positions (PB=16 covers 512; PB=8 used when seqlen<256).
//  - Trapezoid KB=8: lane holds KB-wide left overlap + PB owned; 8 steps
//    between exchanges. Halo = 8 __shfl_up + 1 packed (e,ex,hasmass) int.
//  - W pair-table (16 rows of (W[a],W[b]) float2, PSTR=33 padding) written
//    and read by the same warp: one __syncwarp per 32-step chunk, that's it.
//  - Scaling: per-lane pow2 exponent; mixing at the COMMON scale
//    cc = max(e+ex, eL+exL) folds renorm and rescale into one multiply pass;
//    all factors <= 1 so overflow is impossible; underflow flushes to 0
//    (correct: >=2^126 below the other term).
//  - 2 independent warps (batches) per 64-thread CTA, grid=nb/2=128 -> one
//    CTA per SM, each warp alone on its SMSP.

#define XCH  32
#define KB   8
#define PSTR 33
#define NBAT 2
#define TPB  (32 * NBAT)

__device__ __forceinline__ float exp2i_le(int d) {
    int b = d + 127;
    b = b < 0 ? 0 : (b > 254 ? 254 : b);
    return __int_as_float(b << 23);
}

template<int PB>
__device__ __forceinline__ void scan_batch(
    const float* __restrict__ x, const int* __restrict__ seqs,
    int sl, int bb, int nt, int nb, int ns,
    float* __restrict__ out,
    float2* __restrict__ shP,    // [2][16*PSTR]
    float*  __restrict__ gall,   // [32*PB]
    int*    __restrict__ eall)   // [32]
{
    constexpr int NU = PB + KB - 1;       // updates per step (odd)
    constexpr int NP = (NU + 1) / 2;      // pair rows (last = single, padded)
    const int l    = threadIdx.x & 31;
    const int jmin = l * PB;

    // move indices: update target G[i+1] = position jmin+i+1-KB,
    // uses seqs[jmin+i-KB]
    int s[NU + 1];
    #pragma unroll
    for (int k = 0; k < NU; ++k) {
        int q = jmin + k - KB;
        s[k] = (q >= 0 && q < ns) ? seqs[(long long)bb * ns + q] : 0;
    }
    s[NU] = s[NU - 1];
    int pq[NP];
    #pragma unroll
    for (int q = 0; q < NP; ++q)
        pq[q] = (s[2 * q] * 4 + s[2 * q + 1]) * PSTR;

    float G[KB + PB];
    #pragma unroll
    for (int i = 0; i < KB + PB; ++i) G[i] = 0.0f;
    if (l == 0) G[KB] = 1.0f;             // position 0: fwd=0 -> G=1
    int e = 0;

    float a0 = 0.f, a1 = 0.f, a2 = 0.f, a3 = 0.f, a4 = 0.f;
    double x4s = 0.0;

    auto prefetch = [&](int c) {          // LDG only (regs), one tau per lane
        int tt = c * XCH + l;
        if (tt < nt) {
            const float* xp = x + ((long long)tt * nb + bb) * 5;
            a0 = xp[0]; a1 = xp[1]; a2 = xp[2]; a3 = xp[3]; a4 = xp[4];
        } else {
            a0 = a1 = a2 = a3 = -1e9f;    // exp -> 0: steps past nt freeze G
            a4 = 0.f;
        }
    };
    auto convert = [&](int c) {           // expf + 16 STS.64 pair rows
        float w[4];
        w[0] = __expf(a0 - a4); w[1] = __expf(a1 - a4);
        w[2] = __expf(a2 - a4); w[3] = __expf(a3 - a4);
        float2* row = shP + (c & 1) * (16 * PSTR) + l;
        #pragma unroll
        for (int aa = 0; aa < 4; ++aa)
            #pragma unroll
            for (int bq = 0; bq < 4; ++bq)
                row[(aa * 4 + bq) * PSTR] = make_float2(w[aa], w[bq]);
        if (c * XCH + l < nt) x4s += (double)a4;
    };

    prefetch(0); convert(0); prefetch(1);
    __syncwarp();

    const int NC = (nt + XCH - 1) / XCH;
    for (int c = 0; c < NC; ++c) {
        const float2* cb = shP + (c & 1) * (16 * PSTR);
        #pragma unroll 1
        for (int r = 0; r < XCH / KB; ++r) {
            // ---- exchange (shfl halo, common-scale mixing) ----
            float mx = G[KB];
            #pragma unroll
            for (int i = KB + 1; i < KB + PB; ++i) mx = fmaxf(mx, G[i]);
            int ex = (__float_as_int(mx) >> 23) - 127;
            int hm = (mx > 0.0f) ? 1 : 0;
            int pack  = (e << 9) | ((ex + 128) << 1) | hm;
            int packL = __shfl_up_sync(0xffffffffu, pack, 1);
            float h[KB];
            #pragma unroll
            for (int i = 0; i < KB; ++i)       // left lane's top KB owned
                h[i] = __shfl_up_sync(0xffffffffu, G[PB + i], 1);
            int hL  = (l == 0) ? 0 : (packL & 1);
            int exL = ((packL >> 1) & 255) - 128;
            int eL  = packL >> 9;              // arithmetic: sign preserved
            const int NEG = -(1 << 29);
            int EO = hm ? (e + ex)   : NEG;
            int EL = hL ? (eL + exL) : NEG;
            int cc = EO > EL ? EO : EL;
            if (cc == NEG) cc = 0;
            float rs = exp2i_le(e - cc);       // <= 2^-ex -> post-mix <= 2
            float rl = hL ? exp2i_le(eL - cc) : 0.0f;
            #pragma unroll
            for (int i = 0; i < KB; ++i) G[i] = h[i] * rl;
            #pragma unroll
            for (int i = KB; i < KB + PB; ++i) G[i] *= rs;
            e = cc;

            // ---- ladder: KB steps, pair loads double-buffered ----
            const float2* b2 = cb + r * KB;
            float2 W0[NP], W1[NP];
            #pragma unroll
            for (int q = 0; q < NP; ++q) W0[q] = b2[pq[q]];
            #pragma unroll
            for (int k = 0; k < KB; ++k) {
                float2* cur = (k & 1) ? W1 : W0;
                float2* nxt = (k & 1) ? W0 : W1;
                if (k < KB - 1) {
                    #pragma unroll
                    for (int q = 0; q < NP; ++q) nxt[q] = b2[pq[q] + k + 1];
                }
                // in-place descending: reads are pre-step values
                G[NU] = fmaf(cur[NP - 1].x, G[NU - 1], G[NU]);
                #pragma unroll
                for (int q = NP - 2; q >= 0; --q) {
                    G[2*q + 2] = fmaf(cur[q].y, G[2*q + 1], G[2*q + 2]);
                    G[2*q + 1] = fmaf(cur[q].x, G[2*q],     G[2*q + 1]);
                }
            }
        }
        convert(c + 1);      // uses regs from prefetch(c+1)
        __syncwarp();        // cross-lane table visibility
        prefetch(c + 2);
    }

    // ---- epilogue ----
    #pragma unroll
    for (int i = 0; i < PB; ++i) gall[jmin + i] = G[KB + i];
    eall[l] = e;
    double v = x4s;
    #pragma unroll
    for (int o = 16; o; o >>= 1)
        v += __shfl_down_sync(0xffffffffu, v, o);
    __syncwarp();
    if (l == 0) {
        float  Gv = gall[sl];
        int    ev = eall[sl / PB];
        double lv = (double)logf(Gv) + (double)ev * 0.6931471805599453 + v;
        out[bb] = (float)(-lv / (double)nt);
    }
}

__global__ __launch_bounds__(TPB)
void ctc_fwd(const float* __restrict__ x,
             const int*   __restrict__ seqs,
             const int*   __restrict__ seqlens,
             float*       __restrict__ out,
             int nt, int nb, int ns)
{
    __shared__ float2 shP [NBAT][2 * 16 * PSTR];
    __shared__ float  gall[NBAT][512];
    __shared__ int    eall[NBAT][32];

    const int w  = threadIdx.x >> 5;
    const int bb = blockIdx.x * NBAT + w;
    if (bb >= nb) return;                  // warp-uniform exit
    const int sl = seqlens[bb];

    if (sl < 256)
        scan_batch<8>(x, seqs, sl, bb, nt, nb, ns, out,
                      shP[w], gall[w], eall[w]);
    else
        scan_batch<16>(x, seqs, sl, bb, nt, nb, ns, out,
                       shP[w], gall[w], eall[w]);
}

extern "C" void kernel_launch(void* const* d_in, const int* in_sizes, int n_in,
                              void* d_out, int out_size) {
    const float* x       = (const float*)d_in[0];
    const int*   seqs    = (const int*)  d_in[1];
    const int*   seqlens = (const int*)  d_in[2];
    float*       out     = (float*)d_out;

    const int nb = in_sizes[2];
    const int ns = in_sizes[1] / nb;
    const int nt = in_sizes[0] / (nb * 5);

    ctc_fwd<<<(nb + NBAT - 1) / NBAT, TPB>>>(x, seqs, seqlens, out, nt, nb, ns);
}